// round 15
// baseline (speedup 1.0000x reference)
#include <cuda_runtime.h>
#include <cstring>

#define B_SZ   1024
#define S_SZ   2048
#define F_SZ   9
#define LB_SZ  3
#define T_STEPS 2044   // S - 1 - LB
#define LN_EPS 1e-3f
#define NTHR   1024

// Partial pools: col-groups of 4 cols padded to 36 floats (32 data + 4 pad)
// -> partial STS lane-stride 36 words (4 mod 32) = conflict-free.
#define PG     36
#define P16B   (64 * PG)          // 2304 floats: enc2/upd slice (N=256)
#define P8B    (128 * PG)         // 4608 floats: dec1 slice (N=512)
#define POOL_FLOATS (16 * P16B)   // 36864 ( == 8 * P8B )
#define POOL_BYTES  (POOL_FLOATS * 4)   // 147456

extern __shared__ float pool[];  // 144 KB dynamic scratch (GEMM partials)

// ---------------------------------------------------------------------------
// Packed fp32x2 FMA (Blackwell FFMA2) — only reachable via PTX fma.rn.f32x2
// ---------------------------------------------------------------------------
__device__ __forceinline__ float2 ffma2(float2 a, float2 b, float2 c) {
    unsigned long long ra, rb, rc, rd;
    memcpy(&ra, &a, 8); memcpy(&rb, &b, 8); memcpy(&rc, &c, 8);
    asm("fma.rn.f32x2 %0, %1, %2, %3;" : "=l"(rd) : "l"(ra), "l"(rb), "l"(rc));
    float2 d; memcpy(&d, &rd, 8);
    return d;
}

__device__ __forceinline__ float4 ld4(const float* p) {
    return *reinterpret_cast<const float4*>(p);
}

// fast tanh: (e^{2x}-1)/(e^{2x}+1) via ex2.approx + rcp.approx (~1e-6 err)
__device__ __forceinline__ float fast_tanh(float x) {
    float cx = fminf(fmaxf(x, -9.f), 9.f);
    float t;
    asm("ex2.approx.f32 %0, %1;" : "=f"(t) : "f"(cx * 2.885390082f)); // 2/ln2
    float r;
    asm("rcp.approx.f32 %0, %1;" : "=f"(r) : "f"(t + 1.f));
    return (t - 1.f) * r;
}

// ---------------------------------------------------------------------------
// 4-col x 8-row GEMM k-slice, UB=2 register prefetch (R11 style, fits 64 regs
// at 1024 threads). Per k-row: 2 LDS.128 + 1 LDG.128 + 16 FFMA2.
// partBase[colg*36 + c*8 + m] = sum over k in [k0, k0+CNT).
// ---------------------------------------------------------------------------
template<int LD, int CNT>
__device__ __forceinline__ void gemm4col(const float* __restrict__ A,
                                         const float* __restrict__ W,
                                         int colg, int k0,
                                         float* __restrict__ partBase)
{
    const float* Wp = W + (size_t)k0 * LD + colg * 4;
    const float* Ap = A + k0 * 8;

    float2 acc[4][4];
#pragma unroll
    for (int c = 0; c < 4; ++c)
#pragma unroll
        for (int p = 0; p < 4; ++p) acc[c][p] = make_float2(0.f, 0.f);

    constexpr int UB = 2;
    constexpr int NB = CNT / UB;

    float4 w[UB];
#pragma unroll
    for (int u = 0; u < UB; ++u) w[u] = ld4(Wp + (size_t)u * LD);

#pragma unroll 1
    for (int kb = 0; kb < NB - 1; ++kb) {
        float4 nw[UB];
        const float* Wn = Wp + (size_t)(kb + 1) * UB * LD;
#pragma unroll
        for (int u = 0; u < UB; ++u) nw[u] = ld4(Wn + (size_t)u * LD);
#pragma unroll
        for (int u = 0; u < UB; ++u) {
            const int k = kb * UB + u;
            float4 aA = ld4(Ap + k * 8);
            float4 aB = ld4(Ap + k * 8 + 4);
            float2 r0 = make_float2(aA.x, aA.y), r1 = make_float2(aA.z, aA.w);
            float2 r2 = make_float2(aB.x, aB.y), r3 = make_float2(aB.z, aB.w);
            const float wv[4] = { w[u].x, w[u].y, w[u].z, w[u].w };
#pragma unroll
            for (int c = 0; c < 4; ++c) {
                float2 w2 = make_float2(wv[c], wv[c]);
                acc[c][0] = ffma2(r0, w2, acc[c][0]);
                acc[c][1] = ffma2(r1, w2, acc[c][1]);
                acc[c][2] = ffma2(r2, w2, acc[c][2]);
                acc[c][3] = ffma2(r3, w2, acc[c][3]);
            }
        }
#pragma unroll
        for (int u = 0; u < UB; ++u) w[u] = nw[u];
    }
#pragma unroll
    for (int u = 0; u < UB; ++u) {
        const int k = (NB - 1) * UB + u;
        float4 aA = ld4(Ap + k * 8);
        float4 aB = ld4(Ap + k * 8 + 4);
        float2 r0 = make_float2(aA.x, aA.y), r1 = make_float2(aA.z, aA.w);
        float2 r2 = make_float2(aB.x, aB.y), r3 = make_float2(aB.z, aB.w);
        const float wv[4] = { w[u].x, w[u].y, w[u].z, w[u].w };
#pragma unroll
        for (int c = 0; c < 4; ++c) {
            float2 w2 = make_float2(wv[c], wv[c]);
            acc[c][0] = ffma2(r0, w2, acc[c][0]);
            acc[c][1] = ffma2(r1, w2, acc[c][1]);
            acc[c][2] = ffma2(r2, w2, acc[c][2]);
            acc[c][3] = ffma2(r3, w2, acc[c][3]);
        }
    }
    // remainder (CNT % UB, e.g. 1 for CNT=33)
#pragma unroll
    for (int k = NB * UB; k < CNT; ++k) {
        float4 wr = ld4(Wp + (size_t)k * LD);
        float4 aA = ld4(Ap + k * 8);
        float4 aB = ld4(Ap + k * 8 + 4);
        float2 r0 = make_float2(aA.x, aA.y), r1 = make_float2(aA.z, aA.w);
        float2 r2 = make_float2(aB.x, aB.y), r3 = make_float2(aB.z, aB.w);
        const float wv[4] = { wr.x, wr.y, wr.z, wr.w };
#pragma unroll
        for (int c = 0; c < 4; ++c) {
            float2 w2 = make_float2(wv[c], wv[c]);
            acc[c][0] = ffma2(r0, w2, acc[c][0]);
            acc[c][1] = ffma2(r1, w2, acc[c][1]);
            acc[c][2] = ffma2(r2, w2, acc[c][2]);
            acc[c][3] = ffma2(r3, w2, acc[c][3]);
        }
    }

    float* pp = partBase + colg * PG;
#pragma unroll
    for (int c = 0; c < 4; ++c) {
        *reinterpret_cast<float4*>(pp + c * 8) =
            make_float4(acc[c][0].x, acc[c][0].y, acc[c][1].x, acc[c][1].y);
        *reinterpret_cast<float4*>(pp + c * 8 + 4) =
            make_float4(acc[c][2].x, acc[c][2].y, acc[c][3].x, acc[c][3].y);
    }
}

// Combine 16 slices (stride P16B) + bias -> C[2048]. 1024 thr x float2.
__device__ __forceinline__ void combine16(const float* __restrict__ bias,
                                          float* __restrict__ C)
{
    const int i = threadIdx.x;
    const int n = i >> 2, mp = (i & 3) * 2;
    const int base = (n >> 2) * PG + (n & 3) * 8 + mp;
    float2 s = *reinterpret_cast<const float2*>(pool + base);
#pragma unroll
    for (int o = 1; o < 16; ++o) {
        float2 q = *reinterpret_cast<const float2*>(pool + o * P16B + base);
        s.x += q.x; s.y += q.y;
    }
    float bv = bias[n];
    s.x += bv; s.y += bv;
    *reinterpret_cast<float2*>(C + n * 8 + mp) = s;
}

// Combine 8 slices (stride P8B) + bias + fast_tanh -> C[4096]. 1024 thr x float4.
__device__ __forceinline__ void combine8_tanh(const float* __restrict__ bias,
                                              float* __restrict__ C)
{
    const int i = threadIdx.x;
    const int n = i >> 1, mq = (i & 1) * 4;
    const int base = (n >> 2) * PG + (n & 3) * 8 + mq;
    float4 s = *reinterpret_cast<const float4*>(pool + base);
#pragma unroll
    for (int o = 1; o < 8; ++o) {
        float4 q = *reinterpret_cast<const float4*>(pool + o * P8B + base);
        s.x += q.x; s.y += q.y; s.z += q.z; s.w += q.w;
    }
    float bv = bias[n];
    s.x = fast_tanh(s.x + bv); s.y = fast_tanh(s.y + bv);
    s.z = fast_tanh(s.z + bv); s.w = fast_tanh(s.w + bv);
    *reinterpret_cast<float4*>(C + n * 8 + mq) = s;
}

// ---------------------------------------------------------------------------
// enc1: C[512][8] = tanh(x @ w1 + b1), x from the 3-slot LN'd ring.
// 1024 threads: 2 row-groups (4 rows) x 512 cols x 1 col.
// ---------------------------------------------------------------------------
__device__ __forceinline__ void gemm_enc1(const float* __restrict__ xring,
                                          int step,
                                          const float* __restrict__ W,
                                          const float* __restrict__ bias,
                                          float* __restrict__ C)
{
    const int tid = threadIdx.x;
    const int g   = tid >> 9;           // rows 4g..4g+3
    const int n0  = tid & 511;
    const float* Wp = W + n0;
    const float bv = bias[n0];
    float2 a0 = make_float2(bv, bv), a1 = make_float2(bv, bv);

    const int s0 = step % 3, s1 = (step + 1) % 3, s2 = (step + 2) % 3;
    const float* Abase[3] = { xring + s0 * 88, xring + s1 * 88, xring + s2 * 88 };

#pragma unroll
    for (int j = 0; j < 3; ++j) {
        const float* A = Abase[j] + 4 * g;
#pragma unroll
        for (int c = 0; c < 11; ++c) {
            const int k = j * 11 + c;
            float wv = Wp[(size_t)k * 512];
            float4 av = ld4(A + c * 8);
            float2 w2 = make_float2(wv, wv);
            a0 = ffma2(make_float2(av.x, av.y), w2, a0);
            a1 = ffma2(make_float2(av.z, av.w), w2, a1);
        }
    }
    a0.x = fast_tanh(a0.x); a0.y = fast_tanh(a0.y);
    a1.x = fast_tanh(a1.x); a1.y = fast_tanh(a1.y);
    *reinterpret_cast<float2*>(C + n0 * 8 + 4 * g)     = a0;
    *reinterpret_cast<float2*>(C + n0 * 8 + 4 * g + 2) = a1;
}

// ---------------------------------------------------------------------------
// Persistent kernel: 128 CTAs x 8 batch rows x 1024 threads (occ 50%).
// ---------------------------------------------------------------------------
__global__ __launch_bounds__(NTHR, 1)
void solver_kernel(const float* __restrict__ in0,
                   const float* __restrict__ g1,  const float* __restrict__ be1,
                   const float* __restrict__ w1,  const float* __restrict__ b1,
                   const float* __restrict__ w2,  const float* __restrict__ b2,
                   const float* __restrict__ wu,  const float* __restrict__ bu,
                   const float* __restrict__ g2,  const float* __restrict__ be2,
                   const float* __restrict__ wbeta,
                   const float* __restrict__ wd1, const float* __restrict__ bd1,
                   const float* __restrict__ wd2, const float* __restrict__ bd2,
                   const int*   __restrict__ fix, int nfix,
                   float* __restrict__ out)
{
    __shared__ __align__(16) float xring[3 * 88];    // LN'd x rows, slot = t%3
    __shared__ __align__(16) float buf512[512 * 8];  // h1 / t
    __shared__ __align__(16) float hbuf[256 * 8];    // h / dec2 partials
    __shared__ __align__(16) float comb[257 * 8];    // [LN2(u), ect]
    __shared__ __align__(16) float win[3 * 8 * 8];   // window ring, slot = t%3
    __shared__ __align__(16) float ybuf[8 * 8 * 16]; // 16-step output staging

    const int tid  = threadIdx.x;
    const int wid  = tid >> 5, lane = tid & 31;
    const int b_base = blockIdx.x * 8;

    const int f0 = (nfix > 0) ? fix[0] : -1;
    const int f1 = (nfix > 1) ? fix[1] : -1;

    // init window = inputs[:, 0:3, 1:9]  (row t -> slot t%3 = t for t=0..2)
    for (int idx = tid; idx < 192; idx += NTHR) {
        int j = idx / 64, rem = idx % 64, n = rem >> 3, m = rem & 7;
        win[j * 64 + n * 8 + m] = in0[((size_t)(b_base + m) * S_SZ + j) * F_SZ + 1 + n];
    }
    __syncthreads();

    for (int step = 0; step < T_STEPS; ++step) {
        const int i = step + LB_SZ;
        const int r = step % 3;   // win slot for this step's y

        // ---- LN1: only the NEW row t = step+2 (warmup: all 3) ----
        if (wid < 8) {
            const int m = wid;
            const int jstart = (step == 0) ? 0 : 2;
            for (int j = jstart; j < 3; ++j) {
                const int t = step + j;
                float v = 0.f;
                if (lane < 11) {
                    if (lane < 3) {
                        size_t base = ((size_t)(b_base + m) * S_SZ + t) * F_SZ;
                        float L = in0[base];
                        if (lane < 2) v = L;                      // loading, cumsum
                        else v = (t > 0) ? (L - in0[base - F_SZ]) : 0.f;
                    } else {
                        v = win[(t % 3) * 64 + (lane - 3) * 8 + m];
                    }
                }
                float s = v, s2 = v * v;
#pragma unroll
                for (int off = 16; off > 0; off >>= 1) {
                    s  += __shfl_xor_sync(0xffffffffu, s,  off);
                    s2 += __shfl_xor_sync(0xffffffffu, s2, off);
                }
                float mean = s * (1.f / 11.f);
                float var  = s2 * (1.f / 11.f) - mean * mean;
                float rs   = rsqrtf(var + LN_EPS);
                if (lane < 11)
                    xring[(t % 3) * 88 + lane * 8 + m] =
                        (v - mean) * rs * g1[lane] + be1[lane];
            }
        }
        __syncthreads();

        gemm_enc1(xring, step, w1, b1, buf512);            // h1 = tanh(x@w1+b1)
        __syncthreads();

        // ---- enc2: h = h1@w2 + b2, N=256 K=512, 16-way k-split x 4 cols ----
        {
            const int slice = tid >> 6, colg = tid & 63;
            gemm4col<256, 32>(buf512, w2, colg, slice * 32, pool + slice * P16B);
        }
        __syncthreads();
        combine16(b2, hbuf);
        __syncthreads();

        // ---- upd: u = h@wu + bu partials, 16-way k-split x 4 cols ----
        {
            const int slice = tid >> 6, colg = tid & 63;
            gemm4col<256, 16>(hbuf, wu, colg, slice * 16, pool + slice * P16B);
        }
        __syncthreads();

        // ---- fused combine + LN2(u) + ect = h@beta_w -> comb[257][8] ----
        if (wid < 8) {
            const int m = wid;
            float uv[8];
            float su = 0.f, sq = 0.f, se = 0.f;
#pragma unroll
            for (int q = 0; q < 8; ++q) {
                int n = lane + 32 * q;
                int pb = (n >> 2) * PG + (n & 3) * 8 + m;
                float u = bu[n];
#pragma unroll
                for (int o = 0; o < 16; ++o) u += pool[o * P16B + pb];
                uv[q] = u; su += u; sq += u * u;
                se += hbuf[n * 8 + m] * wbeta[n];
            }
#pragma unroll
            for (int off = 16; off > 0; off >>= 1) {
                su += __shfl_xor_sync(0xffffffffu, su, off);
                sq += __shfl_xor_sync(0xffffffffu, sq, off);
                se += __shfl_xor_sync(0xffffffffu, se, off);
            }
            float mean = su * (1.f / 256.f);
            float var  = sq * (1.f / 256.f) - mean * mean;
            float rs   = rsqrtf(var + LN_EPS);
#pragma unroll
            for (int q = 0; q < 8; ++q) {
                int n = lane + 32 * q;
                comb[n * 8 + m] = (uv[q] - mean) * rs * g2[n] + be2[n];
            }
            if (lane == 0) comb[256 * 8 + m] = se;
        }
        __syncthreads();

        // ---- dec1: t = tanh(comb@wd1 + bd1), N=512 K=257, 8-way split x 4 cols ----
        {
            const int slice = tid >> 7, colg = tid & 127;
            if (slice == 0)
                gemm4col<512, 33>(comb, wd1, colg, 0, pool);
            else
                gemm4col<512, 32>(comb, wd1, colg, slice * 32 + 1, pool + slice * P8B);
        }
        __syncthreads();
        combine8_tanh(bd1, buf512);
        __syncthreads();

        // ---- dec2: y = t@wd2 + bd2, 16-way k-split, partials in hbuf ----
        {
            const int ks = tid >> 6, nm = tid & 63;
            const int n = nm & 7, m = nm >> 3, k0 = ks * 32;
            float a0 = 0.f, a1 = 0.f;
#pragma unroll 8
            for (int k = 0; k < 32; k += 2) {
                a0 += buf512[(k0 + k)     * 8 + m] * wd2[(k0 + k)     * 8 + n];
                a1 += buf512[(k0 + k + 1) * 8 + m] * wd2[(k0 + k + 1) * 8 + n];
            }
            hbuf[ks * 64 + nm] = a0 + a1;
        }
        __syncthreads();
        if (tid < 64) {
            const int n = tid & 7, m = tid >> 3;
            float acc = bd2[n];
#pragma unroll
            for (int ks = 0; ks < 16; ++ks) acc += hbuf[ks * 64 + tid];
            if (n == f0 || n == f1)
                acc = in0[((size_t)(b_base + m) * S_SZ + (i + 1)) * F_SZ + 1 + n];
            ybuf[(n * 8 + m) * 16 + (step & 15)] = acc;
            win[r * 64 + n * 8 + m] = acc;
            // flush own ybuf row (same thread wrote all 16 slots)
            if ((step & 15) == 15) {
                const float4* src = reinterpret_cast<const float4*>(&ybuf[(n * 8 + m) * 16]);
                float4* dst = reinterpret_cast<float4*>(
                    &out[(size_t)n * B_SZ * T_STEPS + (size_t)(b_base + m) * T_STEPS + (step - 15)]);
                dst[0] = src[0]; dst[1] = src[1]; dst[2] = src[2]; dst[3] = src[3];
            }
        }
        __syncthreads();
    }

    // tail flush (T_STEPS % 16 == 12): each thread flushes its own row
    if (tid < 64) {
        const int n = tid & 7, m = tid >> 3;
        const int step0 = (T_STEPS / 16) * 16;
        for (int s2 = 0; s2 < T_STEPS - step0; ++s2)
            out[(size_t)n * B_SZ * T_STEPS + (size_t)(b_base + m) * T_STEPS + step0 + s2]
                = ybuf[(n * 8 + m) * 16 + s2];
    }
}

extern "C" void kernel_launch(void* const* d_in, const int* in_sizes, int n_in,
                              void* d_out, int out_size) {
    const float* in0   = (const float*)d_in[0];
    const float* g1    = (const float*)d_in[1];
    const float* be1   = (const float*)d_in[2];
    const float* w1    = (const float*)d_in[3];
    const float* b1    = (const float*)d_in[4];
    const float* w2    = (const float*)d_in[5];
    const float* b2    = (const float*)d_in[6];
    const float* wu    = (const float*)d_in[7];
    const float* bu    = (const float*)d_in[8];
    const float* g2    = (const float*)d_in[9];
    const float* be2   = (const float*)d_in[10];
    const float* wbeta = (const float*)d_in[11];
    const float* wd1   = (const float*)d_in[12];
    const float* bd1   = (const float*)d_in[13];
    const float* wd2   = (const float*)d_in[14];
    const float* bd2   = (const float*)d_in[15];
    const int*   fix   = (const int*)d_in[16];
    const int    nfix  = in_sizes[16];

    cudaFuncSetAttribute(solver_kernel,
                         cudaFuncAttributeMaxDynamicSharedMemorySize, POOL_BYTES);

    solver_kernel<<<B_SZ / 8, NTHR, POOL_BYTES>>>(
        in0, g1, be1, w1, b1, w2, b2, wu, bu,
        g2, be2, wbeta, wd1, bd1, wd2, bd2,
        fix, nfix, (float*)d_out);
}